// round 1
// baseline (speedup 1.0000x reference)
#include <cuda_runtime.h>

#define N_NODES 50000
#define N_EDGES 800000
#define IN_F    64
#define OUT_F   32
#define N_STEPS 20
#define LR      0.1f
#define SLOPE   0.2f

// ---------------- scratch (device globals; no allocation allowed) ----------------
__device__ float    g_transformed[N_NODES * OUT_F];
__device__ float    g_agg[N_NODES * OUT_F];
__device__ float    g_mu[N_NODES * OUT_F];
__device__ float    g_deg[N_NODES];
__device__ float    g_es[N_NODES];
__device__ float    g_ed[N_NODES];
__device__ unsigned g_mmax[N_NODES];   // order-preserving encoded float max
__device__ float    g_ssum[N_NODES];
__device__ float    g_scores[N_EDGES];
__device__ float    g_evals[N_EDGES];

// Order-preserving float<->uint encoding for atomicMax on floats.
__device__ __forceinline__ unsigned f_enc(float x) {
    unsigned u = __float_as_uint(x);
    return (u & 0x80000000u) ? ~u : (u | 0x80000000u);
}
__device__ __forceinline__ float f_dec(unsigned k) {
    return (k & 0x80000000u) ? __uint_as_float(k & 0x7FFFFFFFu)
                             : __uint_as_float(~k);
}
// encoding of -inf: anything real encodes strictly above this
#define MMAX_INIT 0x007FFFFFu

// ---------------- kernels ----------------

__global__ void init_kernel() {
    int i = blockIdx.x * blockDim.x + threadIdx.x;
    if (i < N_NODES * OUT_F) {
        g_mu[i]  = 0.0f;
        g_agg[i] = 0.0f;
    }
    if (i < N_NODES) g_deg[i] = 0.0f;
}

// transformed = mu_upper @ W^T   (N x 64) @ (64 x 32)
__global__ void gemm_kernel(const float* __restrict__ mu_upper,
                            const float* __restrict__ W) {
    __shared__ float Ws[OUT_F * IN_F];
    for (int i = threadIdx.x; i < OUT_F * IN_F; i += blockDim.x)
        Ws[i] = W[i];
    __syncthreads();

    int tid = blockIdx.x * blockDim.x + threadIdx.x;
    if (tid >= N_NODES * OUT_F) return;
    int n = tid >> 5;          // node
    int f = tid & 31;          // out feature
    const float* row = mu_upper + n * IN_F;
    const float* w   = Ws + f * IN_F;
    float acc = 0.0f;
#pragma unroll
    for (int k = 0; k < IN_F; ++k)
        acc = fmaf(row[k], w[k], acc);
    g_transformed[tid] = acc;
}

__global__ void deg_kernel(const int* __restrict__ dst) {
    int e = blockIdx.x * blockDim.x + threadIdx.x;
    if (e >= N_EDGES) return;
    atomicAdd(&g_deg[dst[e]], 1.0f);
}

// first top-down: alpha0 = 1/(deg[dst]+1e-8); warp per edge, lane = feature
__global__ void topdown0_kernel(const int* __restrict__ src,
                                const int* __restrict__ dst) {
    int t = blockIdx.x * blockDim.x + threadIdx.x;
    int e = t >> 5;
    int lane = t & 31;
    if (e >= N_EDGES) return;
    int sN = src[e], dN = dst[e];
    float alpha = 1.0f / (g_deg[dN] + 1e-8f);
    float v = alpha * g_transformed[sN * OUT_F + lane];
    atomicAdd(&g_agg[dN * OUT_F + lane], v);
}

// per step: mu_hat=relu(agg); err=mu-mu_hat; es=err.a_src; ed=err.a_dst;
// mu -= LR*err;  reset agg / mmax / ssum for the upcoming softmax+aggregate.
__global__ void node_kernel(const float* __restrict__ a_vec) {
    int t = blockIdx.x * blockDim.x + threadIdx.x;
    int n = t >> 5;
    int lane = t & 31;
    if (n >= N_NODES) return;

    float aggv = g_agg[t];
    float mh = fmaxf(aggv, 0.0f);
    float mu = g_mu[t];
    float er = mu - mh;

    float ps = er * a_vec[lane];
    float pd = er * a_vec[OUT_F + lane];
#pragma unroll
    for (int off = 16; off > 0; off >>= 1) {
        ps += __shfl_xor_sync(0xFFFFFFFFu, ps, off);
        pd += __shfl_xor_sync(0xFFFFFFFFu, pd, off);
    }
    if (lane == 0) {
        g_es[n] = ps;
        g_ed[n] = pd;
        g_mmax[n] = MMAX_INIT;
        g_ssum[n] = 0.0f;
    }
    g_mu[t]  = mu - LR * er;
    g_agg[t] = 0.0f;
}

// edge pass A: leaky scores + segment max
__global__ void edge_score_kernel(const int* __restrict__ src,
                                  const int* __restrict__ dst) {
    int e = blockIdx.x * blockDim.x + threadIdx.x;
    if (e >= N_EDGES) return;
    int sN = src[e], dN = dst[e];
    float sc = g_es[sN] + g_ed[dN];
    sc = (sc > 0.0f) ? sc : SLOPE * sc;
    g_scores[e] = sc;
    atomicMax(&g_mmax[dN], f_enc(sc));
}

// edge pass B: e = exp(score - max); segment sum
__global__ void edge_exp_kernel(const int* __restrict__ dst) {
    int e = blockIdx.x * blockDim.x + threadIdx.x;
    if (e >= N_EDGES) return;
    int dN = dst[e];
    float m = f_dec(g_mmax[dN]);
    float ev = __expf(0.0f); // placeholder avoided; use expf below
    ev = expf(g_scores[e] - m);
    g_evals[e] = ev;
    atomicAdd(&g_ssum[dN], ev);
}

// edge pass C: alpha = e/(s+1e-8); aggregate alpha*transformed[src] into agg[dst]
// warp per edge, lane = feature. Optionally emit alpha (final step).
__global__ void edge_agg_kernel(const int* __restrict__ src,
                                const int* __restrict__ dst,
                                float* __restrict__ alpha_out,
                                int write_alpha) {
    int t = blockIdx.x * blockDim.x + threadIdx.x;
    int e = t >> 5;
    int lane = t & 31;
    if (e >= N_EDGES) return;
    int sN = src[e], dN = dst[e];
    float alpha = g_evals[e] / (g_ssum[dN] + 1e-8f);
    if (write_alpha && lane == 0) alpha_out[e] = alpha;
    float v = alpha * g_transformed[sN * OUT_F + lane];
    atomicAdd(&g_agg[dN * OUT_F + lane], v);
}

// final: mu_hat = relu(agg); errors = mu - mu_hat; emit mu + errors
__global__ void final_kernel(float* __restrict__ out_mu,
                             float* __restrict__ out_err) {
    int t = blockIdx.x * blockDim.x + threadIdx.x;
    if (t >= N_NODES * OUT_F) return;
    float mh = fmaxf(g_agg[t], 0.0f);
    float mu = g_mu[t];
    out_mu[t]  = mu;
    out_err[t] = mu - mh;
}

// ---------------- launch ----------------
extern "C" void kernel_launch(void* const* d_in, const int* in_sizes, int n_in,
                              void* d_out, int out_size) {
    const float* mu_upper   = (const float*)d_in[0];
    const float* W          = (const float*)d_in[1];
    const float* a_vec      = (const float*)d_in[2];
    const int*   edge_index = (const int*)d_in[3];
    const int*   src = edge_index;
    const int*   dst = edge_index + N_EDGES;

    float* out       = (float*)d_out;
    float* out_mu    = out;
    float* out_err   = out + N_NODES * OUT_F;
    float* out_alpha = out + 2 * N_NODES * OUT_F;

    const int TPB = 256;
    const int nodeThreads = N_NODES * OUT_F;                 // 1.6M
    const int nodeBlocks  = (nodeThreads + TPB - 1) / TPB;
    const int edgeBlocks  = (N_EDGES + TPB - 1) / TPB;
    const int edgeWarpThreads = N_EDGES * 32;                // 25.6M
    const int edgeWarpBlocks  = (edgeWarpThreads + TPB - 1) / TPB;

    init_kernel<<<nodeBlocks, TPB>>>();
    gemm_kernel<<<nodeBlocks, TPB>>>(mu_upper, W);
    deg_kernel<<<edgeBlocks, TPB>>>(dst);
    topdown0_kernel<<<edgeWarpBlocks, TPB>>>(src, dst);

    for (int t = 0; t < N_STEPS; ++t) {
        node_kernel<<<nodeBlocks, TPB>>>(a_vec);
        edge_score_kernel<<<edgeBlocks, TPB>>>(src, dst);
        edge_exp_kernel<<<edgeBlocks, TPB>>>(dst);
        edge_agg_kernel<<<edgeWarpBlocks, TPB>>>(src, dst, out_alpha,
                                                 (t == N_STEPS - 1) ? 1 : 0);
    }
    final_kernel<<<nodeBlocks, TPB>>>(out_mu, out_err);
}